// round 1
// baseline (speedup 1.0000x reference)
#include <cuda_runtime.h>

#define BATCH 8
#define CH 3
#define HW 262144           // 512*512
#define BC 24               // BATCH*CH
#define NTOT (BC*HW)        // 6291456
#define NBINS 256
#define HW4 (HW/4)          // 65536 float4 per channel
#define BLOCKS_PER_CH 64
#define THREADS 256
#define ITERS 4             // HW4 / (BLOCKS_PER_CH*THREADS)

__device__ int g_hist_s[BC*NBINS];
__device__ int g_hist_r[BC*NBINS];
__device__ float g_lut[BC*NBINS];
__device__ unsigned char g_sq[NTOT];   // quantized ref_masked, reused by loss pass
__device__ double g_acc;

__device__ __forceinline__ int quantize(float x, float m) {
    // to_img: (x+1)*0.5*255, then mask, round-half-even, clip, int
    float img = (x + 1.0f) * 0.5f * 255.0f;
    float v = img * m;
    v = rintf(v);
    v = fminf(fmaxf(v, 0.0f), 255.0f);
    return (int)v;
}

__global__ void zero_kernel() {
    int i = blockIdx.x * blockDim.x + threadIdx.x;   // grid covers BC*NBINS
    g_hist_s[i] = 0;
    g_hist_r[i] = 0;
    if (i == 0) g_acc = 0.0;
}

__global__ void hist_kernel(const float4* __restrict__ tar,
                            const float4* __restrict__ ref,
                            const float4* __restrict__ msrc,
                            const float4* __restrict__ mtar) {
    __shared__ int hs[NBINS];
    __shared__ int hr[NBINS];
    int t = threadIdx.x;
    hs[t] = 0; hr[t] = 0;
    __syncthreads();

    int bc = blockIdx.y;
    int b  = bc / CH;
    int zs = 0, zr = 0;   // bin-0 aggregated in registers (mask-zero hotspot)

    #pragma unroll
    for (int k = 0; k < ITERS; k++) {
        int i4 = blockIdx.x * (THREADS * ITERS) + k * THREADS + t;
        float4 r  = ref [bc * HW4 + i4];
        float4 ta = tar [bc * HW4 + i4];
        float4 ms = msrc[b  * HW4 + i4];
        float4 mt = mtar[b  * HW4 + i4];

        int q0 = quantize(r.x, ms.x);
        int q1 = quantize(r.y, ms.y);
        int q2 = quantize(r.z, ms.z);
        int q3 = quantize(r.w, ms.w);
        ((uchar4*)g_sq)[bc * HW4 + i4] =
            make_uchar4((unsigned char)q0, (unsigned char)q1,
                        (unsigned char)q2, (unsigned char)q3);
        if (q0) atomicAdd(&hs[q0], 1); else zs++;
        if (q1) atomicAdd(&hs[q1], 1); else zs++;
        if (q2) atomicAdd(&hs[q2], 1); else zs++;
        if (q3) atomicAdd(&hs[q3], 1); else zs++;

        int p0 = quantize(ta.x, mt.x);
        int p1 = quantize(ta.y, mt.y);
        int p2 = quantize(ta.z, mt.z);
        int p3 = quantize(ta.w, mt.w);
        if (p0) atomicAdd(&hr[p0], 1); else zr++;
        if (p1) atomicAdd(&hr[p1], 1); else zr++;
        if (p2) atomicAdd(&hr[p2], 1); else zr++;
        if (p3) atomicAdd(&hr[p3], 1); else zr++;
    }

    #pragma unroll
    for (int off = 16; off; off >>= 1) {
        zs += __shfl_down_sync(0xffffffffu, zs, off);
        zr += __shfl_down_sync(0xffffffffu, zr, off);
    }
    if ((t & 31) == 0) {
        if (zs) atomicAdd(&hs[0], zs);
        if (zr) atomicAdd(&hr[0], zr);
    }
    __syncthreads();
    atomicAdd(&g_hist_s[bc * NBINS + t], hs[t]);
    atomicAdd(&g_hist_r[bc * NBINS + t], hr[t]);
}

// One block per channel; 256 threads. Parallel scans + compaction + interp.
__global__ void lut_kernel() {
    int bc = blockIdx.x;
    int t  = threadIdx.x;
    __shared__ int   cs[NBINS], cr[NBINS], posbuf[NBINS];
    __shared__ float sqv[NBINS], rqv[NBINS], xs[NBINS], fs[NBINS];
    __shared__ int firstS, firstR;

    int csv = g_hist_s[bc * NBINS + t];
    int crv = g_hist_r[bc * NBINS + t];
    if (t == 0) { firstS = NBINS; firstR = NBINS; }
    __syncthreads();
    if (csv > 0) atomicMin(&firstS, t);
    if (crv > 0) atomicMin(&firstR, t);
    int noccS = __syncthreads_count(csv > 0);
    int noccR = __syncthreads_count(crv > 0);

    int fS = (firstS == NBINS) ? 0 : firstS;   // argmax of all-false bool = 0
    int fR = (firstR == NBINS) ? 0 : firstR;
    if (t == fS) csv = 0;   // drop smallest unique source value
    if (t == fR) crv = 0;   // drop smallest unique reference value
    cs[t] = csv; cr[t] = crv;
    __syncthreads();

    // inclusive int scans (exact; totals < 2^24)
    for (int off = 1; off < NBINS; off <<= 1) {
        int a  = cs[t];
        int b2 = cr[t];
        int aa = (t >= off) ? cs[t - off] : 0;
        int bb = (t >= off) ? cr[t - off] : 0;
        __syncthreads();
        cs[t] = a + aa; cr[t] = b2 + bb;
        __syncthreads();
    }
    float totS = fmaxf((float)cs[NBINS - 1], 1.0f);
    float totR = fmaxf((float)cr[NBINS - 1], 1.0f);
    sqv[t] = (float)cs[t] / totS;
    rqv[t] = (float)cr[t] / totR;

    // stable compaction of occupied reference bins (excluding fR)
    int flag = (crv > 0) ? 1 : 0;
    posbuf[t] = flag;
    __syncthreads();
    for (int off = 1; off < NBINS; off <<= 1) {
        int a  = posbuf[t];
        int aa = (t >= off) ? posbuf[t - off] : 0;
        __syncthreads();
        posbuf[t] = a + aa;
        __syncthreads();
    }
    xs[t] = 2.0f;   // pads: x>1 so queries (<=1) never reach them
    fs[t] = 0.0f;
    __syncthreads();
    if (flag) { xs[posbuf[t] - 1] = rqv[t]; fs[posbuf[t] - 1] = (float)t; }
    __syncthreads();

    // jnp.interp: i = clip(searchsorted_right(xp,x), 1, 255); f = f0 + (delta/dx)*df
    float x = sqv[t];
    int lo = 0, hi = NBINS;
    while (lo < hi) { int mid = (lo + hi) >> 1; if (xs[mid] <= x) lo = mid + 1; else hi = mid; }
    int i = lo; if (i < 1) i = 1; if (i > NBINS - 1) i = NBINS - 1;
    float x0 = xs[i - 1], x1 = xs[i];
    float f0 = fs[i - 1], f1 = fs[i];
    float dx = x1 - x0;
    float f;
    if (fabsf(dx) <= 1.4210854715202004e-14f) f = f0;   // np.spacing(eps_f32)
    else f = f0 + ((x - x0) / dx) * (f1 - f0);
    if (x < xs[0]) f = fs[0];

    float l = truncf(f);
    if (t == fS) l = 0.0f;                    // interp_value[0] = 0
    if (noccS <= 1 || noccR <= 1) l = 0.0f;   // 'continue' branch -> zeros
    g_lut[bc * NBINS + t] = l;
}

__global__ void loss_kernel(const float4* __restrict__ input,
                            const float4* __restrict__ msrc) {
    __shared__ float lut[NBINS];
    int t  = threadIdx.x;
    int bc = blockIdx.y;
    int b  = bc / CH;
    lut[t] = g_lut[bc * NBINS + t];
    __syncthreads();

    float lsum = 0.0f;
    #pragma unroll
    for (int k = 0; k < ITERS; k++) {
        int i4 = blockIdx.x * (THREADS * ITERS) + k * THREADS + t;
        float4 in = input[bc * HW4 + i4];
        float4 ms = msrc [b  * HW4 + i4];
        uchar4 q  = ((const uchar4*)g_sq)[bc * HW4 + i4];
        lsum += fabsf((in.x + 1.0f) * 0.5f * 255.0f * ms.x - lut[q.x] * ms.x);
        lsum += fabsf((in.y + 1.0f) * 0.5f * 255.0f * ms.y - lut[q.y] * ms.y);
        lsum += fabsf((in.z + 1.0f) * 0.5f * 255.0f * ms.z - lut[q.z] * ms.z);
        lsum += fabsf((in.w + 1.0f) * 0.5f * 255.0f * ms.w - lut[q.w] * ms.w);
    }

    #pragma unroll
    for (int off = 16; off; off >>= 1)
        lsum += __shfl_down_sync(0xffffffffu, lsum, off);
    __shared__ float ws[8];
    if ((t & 31) == 0) ws[t >> 5] = lsum;
    __syncthreads();
    if (t < 8) {
        float v = ws[t];
        #pragma unroll
        for (int off = 4; off; off >>= 1)
            v += __shfl_down_sync(0xffu, v, off);
        if (t == 0) atomicAdd(&g_acc, (double)v);
    }
}

__global__ void final_kernel(float* __restrict__ out) {
    out[0] = (float)(g_acc / (double)NTOT);
}

extern "C" void kernel_launch(void* const* d_in, const int* in_sizes, int n_in,
                              void* d_out, int out_size) {
    const float4* input  = (const float4*)d_in[0];
    const float4* target = (const float4*)d_in[1];
    const float4* ref    = (const float4*)d_in[2];
    const float4* msrc   = (const float4*)d_in[3];
    const float4* mtar   = (const float4*)d_in[4];
    float* out = (float*)d_out;

    zero_kernel<<<BC, NBINS>>>();
    dim3 grid(BLOCKS_PER_CH, BC);
    hist_kernel<<<grid, THREADS>>>(target, ref, msrc, mtar);
    lut_kernel<<<BC, NBINS>>>();
    loss_kernel<<<grid, THREADS>>>(input, msrc);
    final_kernel<<<1, 1>>>(out);
}